// round 3
// baseline (speedup 1.0000x reference)
#include <cuda_runtime.h>

#define BATCH 8
#define N_SEQ 1024
#define CDIM  256
#define RREL  16

// Scratch (device globals — no allocation allowed)
__device__ __align__(16) float g_Gt[CDIM * CDIM];        // Gt[m][k] = sum_c Wq[c][k]*Wk[c][m]
__device__ __align__(16) float g_wu[CDIM];               // Wq^T @ b_k
__device__ __align__(16) float g_wv[CDIM];               // Wk^T @ b_q
__device__ float g_cst;                                  // b_q . b_k
__device__ __align__(16) float g_A[BATCH * N_SEQ * CDIM];// Q @ G  (8 MB)
__device__ __align__(16) float g_u[BATCH * N_SEQ];
__device__ __align__(16) float g_v[BATCH * N_SEQ];

// ---------------------------------------------------------------------------
// prep_gt: Gt[m][k] = sum_c Wq[c][k] * Wk[c][m]   (256x256x256)
// ---------------------------------------------------------------------------
__global__ void prep_gt(const float* __restrict__ Wq, const float* __restrict__ Wk) {
    int bx = blockIdx.x;
    int mt = bx >> 4;
    int kt = bx & 15;
    int tid = threadIdx.x;
    int tm = tid >> 4;
    int tk = tid & 15;
    int lc = tid >> 4;
    int li = tid & 15;

    __shared__ float sq[16][16];
    __shared__ float sk[16][16];

    float acc = 0.f;
    for (int c0 = 0; c0 < CDIM; c0 += 16) {
        sq[lc][li] = Wq[(c0 + lc) * CDIM + kt * 16 + li];
        sk[lc][li] = Wk[(c0 + lc) * CDIM + mt * 16 + li];
        __syncthreads();
#pragma unroll
        for (int cc = 0; cc < 16; cc++)
            acc += sq[cc][tk] * sk[cc][tm];
        __syncthreads();
    }
    g_Gt[(mt * 16 + tm) * CDIM + kt * 16 + tk] = acc;
}

// ---------------------------------------------------------------------------
// prep_vec: wu[k] = sum_c Wq[c][k]*bk[c]; wv[m] = sum_c Wk[c][m]*bq[c]; cst = bq.bk
// ---------------------------------------------------------------------------
__global__ void prep_vec(const float* __restrict__ Wq, const float* __restrict__ Wk,
                         const float* __restrict__ bq, const float* __restrict__ bk) {
    int tid = threadIdx.x;
    float su = 0.f, sv = 0.f;
    for (int c = 0; c < CDIM; c++) {
        su += Wq[c * CDIM + tid] * bk[c];
        sv += Wk[c * CDIM + tid] * bq[c];
    }
    g_wu[tid] = su;
    g_wv[tid] = sv;

    __shared__ float red[256];
    red[tid] = bq[tid] * bk[tid];
    __syncthreads();
    for (int s = 128; s > 0; s >>= 1) {
        if (tid < s) red[tid] += red[tid + s];
        __syncthreads();
    }
    if (tid == 0) g_cst = red[0];
}

// ---------------------------------------------------------------------------
// compute_uv: u[row] = Q[row].wu ; v[row] = K[row].wv  (rows = B*N = 8192)
// ---------------------------------------------------------------------------
__global__ void compute_uv(const float* __restrict__ Q, const float* __restrict__ K) {
    int warp = threadIdx.x >> 5;
    int lane = threadIdx.x & 31;
    int row = blockIdx.x * 8 + warp;
    const float* qr = Q + (size_t)row * CDIM;
    const float* kr = K + (size_t)row * CDIM;
    float au = 0.f, av = 0.f;
#pragma unroll
    for (int t = 0; t < 8; t++) {
        int c = lane + t * 32;
        au += qr[c] * g_wu[c];
        av += kr[c] * g_wv[c];
    }
#pragma unroll
    for (int o = 16; o > 0; o >>= 1) {
        au += __shfl_down_sync(0xffffffffu, au, o);
        av += __shfl_down_sync(0xffffffffu, av, o);
    }
    if (lane == 0) {
        g_u[row] = au;
        g_v[row] = av;
    }
}

// ---------------------------------------------------------------------------
// gemm_A: A[row, m] = sum_k Q[row,k] * Gt[m,k]   (8192 x 256 x 256, NT)
// 128x64 block tile, 8x4 micro, double-buffered. grid (4, 64), 256 thr.
// ---------------------------------------------------------------------------
__global__ __launch_bounds__(256, 2) void gemm_A(const float* __restrict__ Q) {
    int mt = blockIdx.x;          // 0..3  (64 m each)
    int rt = blockIdx.y;          // 0..63 (128 rows each)
    int tid = threadIdx.x;
    int tx = tid & 15;            // m dir   (4 each)
    int ty = tid >> 4;            // row dir (8 each)
    int lrow = tid >> 2;          // 0..63
    int lk = (tid & 3) << 2;      // 0,4,8,12

    __shared__ __align__(16) float As[2][16][128];
    __shared__ __align__(16) float Bs[2][16][64];

    const float* Ap = Q + (size_t)rt * 128 * CDIM;
    const float* Bp = g_Gt + (size_t)mt * 64 * CDIM;

    float4 ra0, ra1, rb0;

    auto ldg_stage = [&](int k0) {
        ra0 = *(const float4*)(Ap + (size_t)lrow * CDIM + k0 + lk);
        ra1 = *(const float4*)(Ap + (size_t)(64 + lrow) * CDIM + k0 + lk);
        rb0 = *(const float4*)(Bp + (size_t)lrow * CDIM + k0 + lk);
    };
    auto sts_stage = [&](int buf) {
        As[buf][lk + 0][lrow] = ra0.x; As[buf][lk + 1][lrow] = ra0.y;
        As[buf][lk + 2][lrow] = ra0.z; As[buf][lk + 3][lrow] = ra0.w;
        As[buf][lk + 0][64 + lrow] = ra1.x; As[buf][lk + 1][64 + lrow] = ra1.y;
        As[buf][lk + 2][64 + lrow] = ra1.z; As[buf][lk + 3][64 + lrow] = ra1.w;
        Bs[buf][lk + 0][lrow] = rb0.x; Bs[buf][lk + 1][lrow] = rb0.y;
        Bs[buf][lk + 2][lrow] = rb0.z; Bs[buf][lk + 3][lrow] = rb0.w;
    };

    float acc[8][4] = {};

    ldg_stage(0);
    sts_stage(0);
    __syncthreads();

    for (int s = 0; s < 16; s++) {
        int cur = s & 1;
        if (s < 15) ldg_stage((s + 1) * 16);
#pragma unroll
        for (int kk = 0; kk < 16; kk++) {
            float4 a0 = *(const float4*)&As[cur][kk][ty * 8];
            float4 a1 = *(const float4*)&As[cur][kk][ty * 8 + 4];
            float4 b0 = *(const float4*)&Bs[cur][kk][tx * 4];
            float av[8] = {a0.x, a0.y, a0.z, a0.w, a1.x, a1.y, a1.z, a1.w};
            float bv[4] = {b0.x, b0.y, b0.z, b0.w};
#pragma unroll
            for (int ii = 0; ii < 8; ii++)
#pragma unroll
                for (int jj = 0; jj < 4; jj++)
                    acc[ii][jj] += av[ii] * bv[jj];
        }
        if (s < 15) {
            __syncthreads();
            sts_stage(cur ^ 1);
            __syncthreads();
        }
    }

    int row = rt * 128 + ty * 8;
    int m = mt * 64 + tx * 4;
#pragma unroll
    for (int ii = 0; ii < 8; ii++) {
        float4 o = {acc[ii][0], acc[ii][1], acc[ii][2], acc[ii][3]};
        *(float4*)&g_A[(size_t)(row + ii) * CDIM + m] = o;
    }
}

// ---------------------------------------------------------------------------
// main_fused: per block (b, it, jt):
//   scores = (A[b,i,:] . Key[b,j,:] + u[i] + v[j] + cst) / 16   (128x128x256)
//   out[b,r,i,j] = scores * R_map[i,j,r]
// grid (8 batch <- fastest for R_map L2 reuse, 64 tiles), 256 threads
// 128x128 tile, 8x8 micro, double-buffered.
// __launch_bounds__(256, 1): full register budget — NO SPILLS (the R2 bug).
// ---------------------------------------------------------------------------
__global__ __launch_bounds__(256, 1) void main_fused(const float* __restrict__ Key,
                                                     const float* __restrict__ Rmap,
                                                     float* __restrict__ out) {
    int b = blockIdx.x;
    int tile = blockIdx.y;
    int it = tile >> 3;
    int jt = tile & 7;
    int tid = threadIdx.x;
    int tx = tid & 15;            // j dir (8 each)
    int ty = tid >> 4;            // i dir (8 each)
    int lrow = tid >> 2;          // 0..63
    int lk = (tid & 3) << 2;      // 0,4,8,12

    __shared__ __align__(16) float As[2][16][128];
    __shared__ __align__(16) float Bs[2][16][128];

    const float* Ap = g_A + ((size_t)b * N_SEQ + it * 128) * CDIM;
    const float* Bp = Key + ((size_t)b * N_SEQ + jt * 128) * CDIM;

    float4 ra0, ra1, rb0, rb1;

    auto ldg_stage = [&](int k0) {
        ra0 = *(const float4*)(Ap + (size_t)lrow * CDIM + k0 + lk);
        ra1 = *(const float4*)(Ap + (size_t)(64 + lrow) * CDIM + k0 + lk);
        rb0 = *(const float4*)(Bp + (size_t)lrow * CDIM + k0 + lk);
        rb1 = *(const float4*)(Bp + (size_t)(64 + lrow) * CDIM + k0 + lk);
    };
    auto sts_stage = [&](int buf) {
        As[buf][lk + 0][lrow] = ra0.x; As[buf][lk + 1][lrow] = ra0.y;
        As[buf][lk + 2][lrow] = ra0.z; As[buf][lk + 3][lrow] = ra0.w;
        As[buf][lk + 0][64 + lrow] = ra1.x; As[buf][lk + 1][64 + lrow] = ra1.y;
        As[buf][lk + 2][64 + lrow] = ra1.z; As[buf][lk + 3][64 + lrow] = ra1.w;
        Bs[buf][lk + 0][lrow] = rb0.x; Bs[buf][lk + 1][lrow] = rb0.y;
        Bs[buf][lk + 2][lrow] = rb0.z; Bs[buf][lk + 3][lrow] = rb0.w;
        Bs[buf][lk + 0][64 + lrow] = rb1.x; Bs[buf][lk + 1][64 + lrow] = rb1.y;
        Bs[buf][lk + 2][64 + lrow] = rb1.z; Bs[buf][lk + 3][64 + lrow] = rb1.w;
    };

    float acc[8][8] = {};

    ldg_stage(0);
    sts_stage(0);
    __syncthreads();

    for (int s = 0; s < 16; s++) {
        int cur = s & 1;
        if (s < 15) ldg_stage((s + 1) * 16);
#pragma unroll
        for (int kk = 0; kk < 16; kk++) {
            float4 a0 = *(const float4*)&As[cur][kk][ty * 8];
            float4 a1 = *(const float4*)&As[cur][kk][ty * 8 + 4];
            float4 b0 = *(const float4*)&Bs[cur][kk][tx * 8];
            float4 b1 = *(const float4*)&Bs[cur][kk][tx * 8 + 4];
            float av[8] = {a0.x, a0.y, a0.z, a0.w, a1.x, a1.y, a1.z, a1.w};
            float bv[8] = {b0.x, b0.y, b0.z, b0.w, b1.x, b1.y, b1.z, b1.w};
#pragma unroll
            for (int ii = 0; ii < 8; ii++)
#pragma unroll
                for (int jj = 0; jj < 8; jj++)
                    acc[ii][jj] += av[ii] * bv[jj];
        }
        if (s < 15) {
            __syncthreads();
            sts_stage(cur ^ 1);
            __syncthreads();
        }
    }

    // ---- epilogue: finalize scores in-place ----
    int i0 = it * 128 + ty * 8;
    int j0 = jt * 128 + tx * 8;
    float cst = g_cst;
    float4 u0 = *(const float4*)&g_u[b * N_SEQ + i0];
    float4 u1 = *(const float4*)&g_u[b * N_SEQ + i0 + 4];
    float4 v0 = *(const float4*)&g_v[b * N_SEQ + j0];
    float4 v1 = *(const float4*)&g_v[b * N_SEQ + j0 + 4];
    float uu[8] = {u0.x, u0.y, u0.z, u0.w, u1.x, u1.y, u1.z, u1.w};
    float vv[8] = {v0.x, v0.y, v0.z, v0.w, v1.x, v1.y, v1.z, v1.w};

#pragma unroll
    for (int ii = 0; ii < 8; ii++)
#pragma unroll
        for (int jj = 0; jj < 8; jj++)
            acc[ii][jj] = (acc[ii][jj] + uu[ii] + vv[jj] + cst) * 0.0625f;

    // ---- relation-mask multiply + streaming store (.cs: keep L2 for R_map) ----
    const size_t NN = (size_t)N_SEQ * N_SEQ;
#pragma unroll
    for (int ii = 0; ii < 8; ii++) {
        int i = i0 + ii;
        const float* rp = Rmap + ((size_t)i * N_SEQ + j0) * RREL;
        float* op = out + (size_t)(b * RREL) * NN + (size_t)i * N_SEQ + j0;
#pragma unroll
        for (int rq = 0; rq < 4; rq++) {
            float qv[32];
#pragma unroll
            for (int jj = 0; jj < 8; jj++) {
                float4 t = *(const float4*)(rp + jj * RREL + rq * 4);
                qv[jj * 4 + 0] = t.x; qv[jj * 4 + 1] = t.y;
                qv[jj * 4 + 2] = t.z; qv[jj * 4 + 3] = t.w;
            }
#pragma unroll
            for (int rr = 0; rr < 4; rr++) {
                int r = rq * 4 + rr;
                float4 o0, o1;
                o0.x = acc[ii][0] * qv[0 * 4 + rr];
                o0.y = acc[ii][1] * qv[1 * 4 + rr];
                o0.z = acc[ii][2] * qv[2 * 4 + rr];
                o0.w = acc[ii][3] * qv[3 * 4 + rr];
                o1.x = acc[ii][4] * qv[4 * 4 + rr];
                o1.y = acc[ii][5] * qv[5 * 4 + rr];
                o1.z = acc[ii][6] * qv[6 * 4 + rr];
                o1.w = acc[ii][7] * qv[7 * 4 + rr];
                float* dst = op + (size_t)r * NN;
                __stcs((float4*)dst, o0);
                __stcs((float4*)(dst + 4), o1);
            }
        }
    }
}

// ---------------------------------------------------------------------------
extern "C" void kernel_launch(void* const* d_in, const int* in_sizes, int n_in,
                              void* d_out, int out_size) {
    const float* Q    = (const float*)d_in[0];
    const float* K    = (const float*)d_in[1];
    const float* Wq   = (const float*)d_in[2];
    const float* bq   = (const float*)d_in[3];
    const float* Wk   = (const float*)d_in[4];
    const float* bk   = (const float*)d_in[5];
    const float* Rmap = (const float*)d_in[6];
    float* out = (float*)d_out;

    prep_gt<<<256, 256>>>(Wq, Wk);
    prep_vec<<<1, 256>>>(Wq, Wk, bq, bk);
    compute_uv<<<1024, 256>>>(Q, K);
    gemm_A<<<dim3(4, 64), 256>>>(Q);
    main_fused<<<dim3(8, 64), 256>>>(K, Rmap, out);
}

// round 4
// speedup vs baseline: 1.2330x; 1.2330x over previous
#include <cuda_runtime.h>

#define BATCH 8
#define N_SEQ 1024
#define CDIM  256
#define RREL  16

// Scratch (device globals — no allocation allowed)
__device__ __align__(16) float g_Gt[CDIM * CDIM];        // Gt[m][k] = sum_c Wq[c][k]*Wk[c][m]
__device__ __align__(16) float g_wu[CDIM];               // Wq^T @ b_k
__device__ __align__(16) float g_wv[CDIM];               // Wk^T @ b_q
__device__ float g_cst;                                  // b_q . b_k
__device__ __align__(16) float g_A[BATCH * N_SEQ * CDIM];// Q @ G  (8 MB)
__device__ __align__(16) float g_u[BATCH * N_SEQ];
__device__ __align__(16) float g_v[BATCH * N_SEQ];

// ---------------------------------------------------------------------------
// prep_gt: Gt[m][k] = sum_c Wq[c][k] * Wk[c][m]   (256x256x256)
// ---------------------------------------------------------------------------
__global__ void prep_gt(const float* __restrict__ Wq, const float* __restrict__ Wk) {
    int bx = blockIdx.x;
    int mt = bx >> 4;
    int kt = bx & 15;
    int tid = threadIdx.x;
    int tm = tid >> 4;
    int tk = tid & 15;
    int lc = tid >> 4;
    int li = tid & 15;

    __shared__ float sq[16][16];
    __shared__ float sk[16][16];

    float acc = 0.f;
    for (int c0 = 0; c0 < CDIM; c0 += 16) {
        sq[lc][li] = Wq[(c0 + lc) * CDIM + kt * 16 + li];
        sk[lc][li] = Wk[(c0 + lc) * CDIM + mt * 16 + li];
        __syncthreads();
#pragma unroll
        for (int cc = 0; cc < 16; cc++)
            acc += sq[cc][tk] * sk[cc][tm];
        __syncthreads();
    }
    g_Gt[(mt * 16 + tm) * CDIM + kt * 16 + tk] = acc;
}

// ---------------------------------------------------------------------------
// prep_vec: wu[k] = sum_c Wq[c][k]*bk[c]; wv[m] = sum_c Wk[c][m]*bq[c]; cst = bq.bk
// ---------------------------------------------------------------------------
__global__ void prep_vec(const float* __restrict__ Wq, const float* __restrict__ Wk,
                         const float* __restrict__ bq, const float* __restrict__ bk) {
    int tid = threadIdx.x;
    float su = 0.f, sv = 0.f;
    for (int c = 0; c < CDIM; c++) {
        su += Wq[c * CDIM + tid] * bk[c];
        sv += Wk[c * CDIM + tid] * bq[c];
    }
    g_wu[tid] = su;
    g_wv[tid] = sv;

    __shared__ float red[256];
    red[tid] = bq[tid] * bk[tid];
    __syncthreads();
    for (int s = 128; s > 0; s >>= 1) {
        if (tid < s) red[tid] += red[tid + s];
        __syncthreads();
    }
    if (tid == 0) g_cst = red[0];
}

// ---------------------------------------------------------------------------
// compute_uv: u[row] = Q[row].wu ; v[row] = K[row].wv  (rows = B*N = 8192)
// ---------------------------------------------------------------------------
__global__ void compute_uv(const float* __restrict__ Q, const float* __restrict__ K) {
    int warp = threadIdx.x >> 5;
    int lane = threadIdx.x & 31;
    int row = blockIdx.x * 8 + warp;
    const float* qr = Q + (size_t)row * CDIM;
    const float* kr = K + (size_t)row * CDIM;
    float au = 0.f, av = 0.f;
#pragma unroll
    for (int t = 0; t < 8; t++) {
        int c = lane + t * 32;
        au += qr[c] * g_wu[c];
        av += kr[c] * g_wv[c];
    }
#pragma unroll
    for (int o = 16; o > 0; o >>= 1) {
        au += __shfl_down_sync(0xffffffffu, au, o);
        av += __shfl_down_sync(0xffffffffu, av, o);
    }
    if (lane == 0) {
        g_u[row] = au;
        g_v[row] = av;
    }
}

// ---------------------------------------------------------------------------
// gemm_A: A[row, m] = sum_k Q[row,k] * Gt[m,k]   (8192 x 256 x 256, NT)
// 128x64 block tile, 8x4 micro, double-buffered. grid (4, 64), 256 thr.
// ---------------------------------------------------------------------------
__global__ __launch_bounds__(256, 2) void gemm_A(const float* __restrict__ Q) {
    int mt = blockIdx.x;
    int rt = blockIdx.y;
    int tid = threadIdx.x;
    int tx = tid & 15;
    int ty = tid >> 4;
    int lrow = tid >> 2;
    int lk = (tid & 3) << 2;

    __shared__ __align__(16) float As[2][16][128];
    __shared__ __align__(16) float Bs[2][16][64];

    const float* Ap = Q + (size_t)rt * 128 * CDIM;
    const float* Bp = g_Gt + (size_t)mt * 64 * CDIM;

    float4 ra0, ra1, rb0;

    auto ldg_stage = [&](int k0) {
        ra0 = *(const float4*)(Ap + (size_t)lrow * CDIM + k0 + lk);
        ra1 = *(const float4*)(Ap + (size_t)(64 + lrow) * CDIM + k0 + lk);
        rb0 = *(const float4*)(Bp + (size_t)lrow * CDIM + k0 + lk);
    };
    auto sts_stage = [&](int buf) {
        As[buf][lk + 0][lrow] = ra0.x; As[buf][lk + 1][lrow] = ra0.y;
        As[buf][lk + 2][lrow] = ra0.z; As[buf][lk + 3][lrow] = ra0.w;
        As[buf][lk + 0][64 + lrow] = ra1.x; As[buf][lk + 1][64 + lrow] = ra1.y;
        As[buf][lk + 2][64 + lrow] = ra1.z; As[buf][lk + 3][64 + lrow] = ra1.w;
        Bs[buf][lk + 0][lrow] = rb0.x; Bs[buf][lk + 1][lrow] = rb0.y;
        Bs[buf][lk + 2][lrow] = rb0.z; Bs[buf][lk + 3][lrow] = rb0.w;
    };

    float acc[8][4] = {};

    ldg_stage(0);
    sts_stage(0);
    __syncthreads();

    for (int s = 0; s < 16; s++) {
        int cur = s & 1;
        if (s < 15) ldg_stage((s + 1) * 16);
#pragma unroll
        for (int kk = 0; kk < 16; kk++) {
            float4 a0 = *(const float4*)&As[cur][kk][ty * 8];
            float4 a1 = *(const float4*)&As[cur][kk][ty * 8 + 4];
            float4 b0 = *(const float4*)&Bs[cur][kk][tx * 4];
            float av[8] = {a0.x, a0.y, a0.z, a0.w, a1.x, a1.y, a1.z, a1.w};
            float bv[4] = {b0.x, b0.y, b0.z, b0.w};
#pragma unroll
            for (int ii = 0; ii < 8; ii++)
#pragma unroll
                for (int jj = 0; jj < 4; jj++)
                    acc[ii][jj] += av[ii] * bv[jj];
        }
        if (s < 15) {
            sts_stage(cur ^ 1);
            __syncthreads();
        }
    }

    int row = rt * 128 + ty * 8;
    int m = mt * 64 + tx * 4;
#pragma unroll
    for (int ii = 0; ii < 8; ii++) {
        float4 o = {acc[ii][0], acc[ii][1], acc[ii][2], acc[ii][3]};
        *(float4*)&g_A[(size_t)(row + ii) * CDIM + m] = o;
    }
}

// ---------------------------------------------------------------------------
// main_fused v4: 64x64 tile, 4x4 micro, double-buffered smem with ONE barrier
// per stage, occ-3 (launch_bounds(256,3)) so epilogue stores of one CTA
// overlap GEMM FMA of co-resident CTAs. 2048 blocks stagger phases.
//   scores = (A[b,i,:] . Key[b,j,:] + u[i] + v[j] + cst) / 16
//   out[b,r,i,j] = scores * R_map[i,j,r]
// grid (8 batch <- fastest for R_map L2 reuse, 256 tiles), 256 threads
// ---------------------------------------------------------------------------
__global__ __launch_bounds__(256, 3) void main_fused(const float* __restrict__ Key,
                                                     const float* __restrict__ Rmap,
                                                     float* __restrict__ out) {
    int b = blockIdx.x;
    int tile = blockIdx.y;
    int it = tile >> 4;
    int jt = tile & 15;
    int tid = threadIdx.x;
    int tx = tid & 15;            // j dir (4 each)
    int ty = tid >> 4;            // i dir (4 each)
    int lrow = tid >> 2;          // 0..63
    int lk = (tid & 3) << 2;      // 0,4,8,12

    __shared__ __align__(16) float As[2][16][64];  // [buf][k][i]
    __shared__ __align__(16) float Bs[2][16][64];  // [buf][k][j]

    const float* Ap = g_A + ((size_t)b * N_SEQ + it * 64) * CDIM;
    const float* Bp = Key + ((size_t)b * N_SEQ + jt * 64) * CDIM;

    float4 ra, rb;

    auto ldg_stage = [&](int k0) {
        ra = *(const float4*)(Ap + (size_t)lrow * CDIM + k0 + lk);
        rb = *(const float4*)(Bp + (size_t)lrow * CDIM + k0 + lk);
    };
    auto sts_stage = [&](int buf) {
        As[buf][lk + 0][lrow] = ra.x; As[buf][lk + 1][lrow] = ra.y;
        As[buf][lk + 2][lrow] = ra.z; As[buf][lk + 3][lrow] = ra.w;
        Bs[buf][lk + 0][lrow] = rb.x; Bs[buf][lk + 1][lrow] = rb.y;
        Bs[buf][lk + 2][lrow] = rb.z; Bs[buf][lk + 3][lrow] = rb.w;
    };

    float acc[4][4] = {};

    ldg_stage(0);
    sts_stage(0);
    __syncthreads();

    for (int s = 0; s < 16; s++) {
        int cur = s & 1;
        if (s < 15) ldg_stage((s + 1) * 16);
#pragma unroll
        for (int kk = 0; kk < 16; kk++) {
            float4 a0 = *(const float4*)&As[cur][kk][ty * 4];
            float4 b0 = *(const float4*)&Bs[cur][kk][tx * 4];
            float av[4] = {a0.x, a0.y, a0.z, a0.w};
            float bv[4] = {b0.x, b0.y, b0.z, b0.w};
#pragma unroll
            for (int ii = 0; ii < 4; ii++)
#pragma unroll
                for (int jj = 0; jj < 4; jj++)
                    acc[ii][jj] += av[ii] * bv[jj];
        }
        if (s < 15) {
            sts_stage(cur ^ 1);    // ping-pong: safe to write other buffer
            __syncthreads();       // single barrier per stage
        }
    }

    // ---- epilogue: finalize scores ----
    int i0 = it * 64 + ty * 4;
    int j0 = jt * 64 + tx * 4;
    float cst = g_cst;
    float4 u0 = *(const float4*)&g_u[b * N_SEQ + i0];
    float4 v0 = *(const float4*)&g_v[b * N_SEQ + j0];
    float uu[4] = {u0.x, u0.y, u0.z, u0.w};
    float vv[4] = {v0.x, v0.y, v0.z, v0.w};

#pragma unroll
    for (int ii = 0; ii < 4; ii++)
#pragma unroll
        for (int jj = 0; jj < 4; jj++)
            acc[ii][jj] = (acc[ii][jj] + uu[ii] + vv[jj] + cst) * 0.0625f;

    // ---- relation-mask multiply + streaming store ----
    const size_t NN = (size_t)N_SEQ * N_SEQ;
#pragma unroll
    for (int ii = 0; ii < 4; ii++) {
        int i = i0 + ii;
        const float* rp = Rmap + ((size_t)i * N_SEQ + j0) * RREL;
        float* op = out + (size_t)(b * RREL) * NN + (size_t)i * N_SEQ + j0;
#pragma unroll
        for (int rq = 0; rq < 4; rq++) {
            float4 t0 = *(const float4*)(rp + 0 * RREL + rq * 4);
            float4 t1 = *(const float4*)(rp + 1 * RREL + rq * 4);
            float4 t2 = *(const float4*)(rp + 2 * RREL + rq * 4);
            float4 t3 = *(const float4*)(rp + 3 * RREL + rq * 4);
            float q0[4] = {t0.x, t0.y, t0.z, t0.w};
            float q1[4] = {t1.x, t1.y, t1.z, t1.w};
            float q2[4] = {t2.x, t2.y, t2.z, t2.w};
            float q3[4] = {t3.x, t3.y, t3.z, t3.w};
#pragma unroll
            for (int rr = 0; rr < 4; rr++) {
                int r = rq * 4 + rr;
                float4 o;
                o.x = acc[ii][0] * q0[rr];
                o.y = acc[ii][1] * q1[rr];
                o.z = acc[ii][2] * q2[rr];
                o.w = acc[ii][3] * q3[rr];
                __stcs((float4*)(op + (size_t)r * NN), o);
            }
        }
    }
}

// ---------------------------------------------------------------------------
extern "C" void kernel_launch(void* const* d_in, const int* in_sizes, int n_in,
                              void* d_out, int out_size) {
    const float* Q    = (const float*)d_in[0];
    const float* K    = (const float*)d_in[1];
    const float* Wq   = (const float*)d_in[2];
    const float* bq   = (const float*)d_in[3];
    const float* Wk   = (const float*)d_in[4];
    const float* bk   = (const float*)d_in[5];
    const float* Rmap = (const float*)d_in[6];
    float* out = (float*)d_out;

    prep_gt<<<256, 256>>>(Wq, Wk);
    prep_vec<<<1, 256>>>(Wq, Wk, bq, bk);
    compute_uv<<<1024, 256>>>(Q, K);
    gemm_A<<<dim3(4, 64), 256>>>(Q);
    main_fused<<<dim3(8, 256), 256>>>(K, Rmap, out);
}